// round 14
// baseline (speedup 1.0000x reference)
#include <cuda_runtime.h>
#include <math.h>

#define TOPK 20
#define MAXB 128
#define MAXS 100
#define SMALL_BLK 64
#define NCHUNK 8

// ---- device scratch (static; no allocations allowed) ----
__device__ float  d_prmf[MAXB * 6];
__device__ double d_prmd[MAXB * 6];
__device__ float  d_vfullf[MAXB * 9];
__device__ double d_prod[MAXB * MAXS];
__device__ double d_sum4P[MAXB * NCHUNK * 4];
__device__ double d_dist2P[MAXB * NCHUNK * 2];
__device__ float  d_gramP[MAXB * NCHUNK * 45];
__device__ float  d_candv[MAXB * NCHUNK * TOPK];
__device__ int    d_candi[MAXB * NCHUNK * TOPK];

__device__ __forceinline__ float fsqrt_fast(float x) {
    return x * rsqrtf(fmaxf(x, 1e-30f));
}

#define IXU(i, j) ((i) * 9 - (i) * ((i) - 1) / 2 + ((j) - (i)))
#define IXE(k, p) (((k) < (p)) ? IXU(k, p) : IXU(p, k))

// =============================== 9x9 smallest-eig solver ===============================
// Register Jacobi (eigenvalues only) + PD-shifted LDL^T (register-resident) +
// 2 inverse-iteration solves. stash = strided shared for G45.
__device__ void solve9reg(const float G45in[45], float* stash, float v[9]) {
#pragma unroll
    for (int i = 0; i < 45; i++) stash[i * SMALL_BLK] = G45in[i];

    float U[45];
#pragma unroll
    for (int i = 0; i < 45; i++) U[i] = G45in[i];

#pragma unroll 1
    for (int sweep = 0; sweep < 10; sweep++) {
        float off = 0.f, dd = 0.f;
#pragma unroll
        for (int p = 0; p < 9; p++) {
            dd += fabsf(U[IXU(p, p)]);
#pragma unroll
            for (int q = p + 1; q < 9; q++) off += fabsf(U[IXU(p, q)]);
        }
        if (off <= 1e-7f * dd) break;
#pragma unroll
        for (int p = 0; p < 8; p++) {
#pragma unroll
            for (int q = p + 1; q < 9; q++) {
                float apq = U[IXU(p, q)];
                float app = U[IXU(p, p)], aqq = U[IXU(q, q)];
                float d = aqq - app;
                float sum = d * d + 4.f * apq * apq;
                float ir = rsqrtf(fmaxf(sum, 1e-37f));
                bool ok = (sum >= 1e-30f);
                float c2 = ok ? (0.5f + 0.5f * fabsf(d) * ir) : 1.f;
                float sgn = (d >= 0.f) ? 1.f : -1.f;
                float sc = ok ? (apq * sgn * ir) : 0.f;
                float icc = rsqrtf(c2);
                float cc = c2 * icc;
                float ss = sc * icc;
                float s2 = 1.f - c2;
                float t2 = 2.f * sc * apq;
                U[IXU(p, p)] = c2 * app + s2 * aqq - t2;
                U[IXU(q, q)] = s2 * app + c2 * aqq + t2;
                U[IXU(p, q)] = 0.f;
#pragma unroll
                for (int k = 0; k < 9; k++) {
                    if (k != p && k != q) {
                        float akp = U[IXE(k, p)], akq = U[IXE(k, q)];
                        U[IXE(k, p)] = cc * akp - ss * akq;
                        U[IXE(k, q)] = ss * akp + cc * akq;
                    }
                }
            }
        }
    }
    float lam = U[IXU(0, 0)];
    float dia = fabsf(U[IXU(0, 0)]);
#pragma unroll
    for (int i = 1; i < 9; i++) {
        lam = fminf(lam, U[IXU(i, i)]);
        dia += fabsf(U[IXU(i, i)]);
    }

    float L[45];
#pragma unroll
    for (int i = 0; i < 45; i++) L[i] = stash[i * SMALL_BLK];
    float shift = lam - 2e-7f * dia - 1e-32f;
#pragma unroll
    for (int i = 0; i < 9; i++) L[IXU(i, i)] -= shift;

    float idg[9];
    float eps_piv = 1e-9f * dia + 1e-35f;
#pragma unroll
    for (int k = 0; k < 9; k++) {
        float d = fmaxf(L[IXU(k, k)], eps_piv);
        float inv = __fdividef(1.f, d);
        idg[k] = inv;
#pragma unroll
        for (int i = k + 1; i < 9; i++) {
            float lik = L[IXU(k, i)] * inv;
#pragma unroll
            for (int j = i; j < 9; j++)
                L[IXU(i, j)] -= lik * L[IXU(k, j)];
            L[IXU(k, i)] = lik;
        }
    }

    float x[9];
#pragma unroll
    for (int i = 0; i < 9; i++) x[i] = 1.f;
#pragma unroll 1
    for (int pass = 0; pass < 2; pass++) {
#pragma unroll
        for (int k = 0; k < 9; k++)
#pragma unroll
            for (int i = k + 1; i < 9; i++)
                x[i] -= L[IXU(k, i)] * x[k];
#pragma unroll
        for (int i = 0; i < 9; i++) x[i] *= idg[i];
#pragma unroll
        for (int k = 8; k >= 0; k--)
#pragma unroll
            for (int j = k + 1; j < 9; j++)
                x[k] -= L[IXU(k, j)] * x[j];
        float am = 0.f;
#pragma unroll
        for (int i = 0; i < 9; i++) am = fmaxf(am, fabsf(x[i]));
        float iam = __fdividef(1.f, am + 1e-37f);
        float n2 = 0.f;
#pragma unroll
        for (int i = 0; i < 9; i++) { float y = x[i] * iam; x[i] = y; n2 += y * y; }
        float inr = rsqrtf(n2);
#pragma unroll
        for (int i = 0; i < 9; i++) x[i] *= inr;
    }
#pragma unroll
    for (int i = 0; i < 9; i++) v[i] = x[i];
}

__device__ __forceinline__ void sign_fix9f(float v[9]) {
    float am = fabsf(v[0]);
    float sv = v[0];
#pragma unroll
    for (int i = 1; i < 9; i++) {
        float a = fabsf(v[i]);
        if (a > am) { am = a; sv = v[i]; }
    }
    if (sv < 0.f) {
#pragma unroll
        for (int i = 0; i < 9; i++) v[i] = -v[i];
    }
}

__device__ void jacobi3f(float* A, float* V) {
#pragma unroll
    for (int i = 0; i < 9; i++) V[i] = (i % 4 == 0) ? 1.f : 0.f;
#define ROT3(p, q)                                                        \
    {                                                                     \
        float apq = A[(p) * 3 + (q)];                                     \
        float app = A[(p) * 3 + (p)], aqq = A[(q) * 3 + (q)];             \
        float d = aqq - app;                                              \
        float sum = d * d + 4.f * apq * apq;                              \
        float ir = rsqrtf(fmaxf(sum, 1e-37f));                            \
        bool ok = (sum >= 1e-30f) && (fabsf(apq) > 1e-30f);               \
        float c2 = ok ? (0.5f + 0.5f * fabsf(d) * ir) : 1.f;              \
        float sgn = (d >= 0.f) ? 1.f : -1.f;                              \
        float sc = ok ? (apq * sgn * ir) : 0.f;                           \
        float icc = rsqrtf(c2);                                           \
        float cc = c2 * icc, ss = sc * icc;                               \
        _Pragma("unroll") for (int k = 0; k < 3; k++) {                   \
            float akp = A[k * 3 + (p)], akq = A[k * 3 + (q)];             \
            A[k * 3 + (p)] = cc * akp - ss * akq;                         \
            A[k * 3 + (q)] = ss * akp + cc * akq;                         \
        }                                                                 \
        _Pragma("unroll") for (int k = 0; k < 3; k++) {                   \
            float apk = A[(p) * 3 + k], aqk = A[(q) * 3 + k];             \
            A[(p) * 3 + k] = cc * apk - ss * aqk;                         \
            A[(q) * 3 + k] = ss * apk + cc * aqk;                         \
        }                                                                 \
        _Pragma("unroll") for (int k = 0; k < 3; k++) {                   \
            float vkp = V[k * 3 + (p)], vkq = V[k * 3 + (q)];             \
            V[k * 3 + (p)] = cc * vkp - ss * vkq;                         \
            V[k * 3 + (q)] = ss * vkp + cc * vkq;                         \
        }                                                                 \
    }
#pragma unroll 1
    for (int sweep = 0; sweep < 8; sweep++) {
        float off = fabsf(A[1]) + fabsf(A[2]) + fabsf(A[5]);
        float dia = fabsf(A[0]) + fabsf(A[4]) + fabsf(A[8]);
        if (off <= 1e-9f * dia) break;
        ROT3(0, 1);
        ROT3(0, 2);
        ROT3(1, 2);
    }
#undef ROT3
}

__device__ void finalize_F(const float vf[9], double s1, double c1x, double c1y,
                           double s2, double c2x, double c2y, float* out9) {
    float F[9];
#pragma unroll
    for (int i = 0; i < 9; i++) F[i] = vf[i];
    float M3[9];
#pragma unroll
    for (int i = 0; i < 3; i++)
#pragma unroll
        for (int j = 0; j < 3; j++) {
            float acc = 0.f;
#pragma unroll
            for (int k = 0; k < 3; k++) acc += F[k * 3 + i] * F[k * 3 + j];
            M3[i * 3 + j] = acc;
        }
    float V3[9];
    jacobi3f(M3, V3);
    float w0 = V3[0], w1 = V3[3], w2 = V3[6];
    float dmin = M3[0];
    if (M3[4] < dmin) { dmin = M3[4]; w0 = V3[1]; w1 = V3[4]; w2 = V3[7]; }
    if (M3[8] < dmin) { w0 = V3[2]; w1 = V3[5]; w2 = V3[8]; }
    float Fw[3];
#pragma unroll
    for (int i = 0; i < 3; i++)
        Fw[i] = F[i * 3 + 0] * w0 + F[i * 3 + 1] * w1 + F[i * 3 + 2] * w2;
    double Fp[9];
#pragma unroll
    for (int i = 0; i < 3; i++) {
        Fp[i * 3 + 0] = (double)(F[i * 3 + 0] - Fw[i] * w0);
        Fp[i * 3 + 1] = (double)(F[i * 3 + 1] - Fw[i] * w1);
        Fp[i * 3 + 2] = (double)(F[i * 3 + 2] - Fw[i] * w2);
    }
    double A[9];
#pragma unroll
    for (int i = 0; i < 3; i++) {
        A[i * 3 + 0] = s1 * Fp[i * 3 + 0];
        A[i * 3 + 1] = s1 * Fp[i * 3 + 1];
        A[i * 3 + 2] = -c1x * s1 * Fp[i * 3 + 0] - c1y * s1 * Fp[i * 3 + 1] + Fp[i * 3 + 2];
    }
#pragma unroll
    for (int j = 0; j < 3; j++) {
        out9[0 * 3 + j] = (float)(s2 * A[0 * 3 + j]);
        out9[1 * 3 + j] = (float)(s2 * A[1 * 3 + j]);
        out9[2 * 3 + j] = (float)(-c2x * s2 * A[0 * 3 + j] - c2y * s2 * A[1 * 3 + j] + A[2 * 3 + j]);
    }
}

// =============================== packed block reductions ===============================
template <int K>
__device__ void blockReduceKD(double* vals, double* sh) {
    __syncthreads();
#pragma unroll
    for (int o = 16; o > 0; o >>= 1) {
#pragma unroll
        for (int k = 0; k < K; k++)
            vals[k] += __shfl_down_sync(0xffffffffu, vals[k], o);
    }
    int wi = threadIdx.x >> 5, li = threadIdx.x & 31;
    if (li == 0) {
#pragma unroll
        for (int k = 0; k < K; k++) sh[wi * K + k] = vals[k];
    }
    __syncthreads();
    if (threadIdx.x == 0) {
        double r[K];
#pragma unroll
        for (int k = 0; k < K; k++) r[k] = 0.0;
        int nw = (blockDim.x + 31) >> 5;
        for (int i = 0; i < nw; i++)
#pragma unroll
            for (int k = 0; k < K; k++) r[k] += sh[i * K + k];
#pragma unroll
        for (int k = 0; k < K; k++) sh[k] = r[k];
    }
    __syncthreads();
#pragma unroll
    for (int k = 0; k < K; k++) vals[k] = sh[k];
}

// =============================== pre-pass kernels (grid = B * NCHUNK) ===============================

// pre1: per-chunk coordinate sums + per-chunk sorted top-20 candidates
__global__ __launch_bounds__(256) void pre1_kernel(
    const float* __restrict__ pts1, const float* __restrict__ pts2,
    const float* __restrict__ wt, const int* __restrict__ un, int N) {
    int b = blockIdx.x / NCHUNK;
    int c = blockIdx.x % NCHUNK;
    int L = (N + NCHUNK - 1) / NCHUNK;
    int n0 = c * L;
    int n1 = min(N, n0 + L);
    int tid = threadIdx.x;

    __shared__ double sh[32];
    __shared__ float sv[256 * TOPK];
    __shared__ int si[256 * TOPK];
    __shared__ float swv[8];
    __shared__ int swi[8];
    __shared__ int s_wini;

    const float* P1 = pts1 + (size_t)b * N * 3;
    const float* P2 = pts2 + (size_t)b * N * 3;
    const float* W = wt + (size_t)b * N;

    // coordinate sums over chunk
    {
        float lx1 = 0.f, ly1 = 0.f, lx2 = 0.f, ly2 = 0.f;
        for (int n = n0 + tid; n < n1; n += 256) {
            lx1 += P1[n * 3 + 0]; ly1 += P1[n * 3 + 1];
            lx2 += P2[n * 3 + 0]; ly2 += P2[n * 3 + 1];
        }
        double c4[4] = { (double)lx1, (double)ly1, (double)lx2, (double)ly2 };
        blockReduceKD<4>(c4, sh);
        if (tid == 0) {
#pragma unroll
            for (int k = 0; k < 4; k++) d_sum4P[(b * NCHUNK + c) * 4 + k] = c4[k];
        }
    }

    // chunk top-20
    {
        int u = un[b];
        float lv[TOPK];
        int li[TOPK];
#pragma unroll
        for (int j = 0; j < TOPK; j++) { lv[j] = -INFINITY; li[j] = 0x7fffffff; }
        for (int n = n0 + tid; n < n1; n += 256) {
            float w = (n < u) ? W[n] : -INFINITY;
            if (w > lv[TOPK - 1]) {
                float cv = w; int ci = n;
#pragma unroll
                for (int j = 0; j < TOPK; j++) {
                    if (cv > lv[j]) {
                        float tf = lv[j]; lv[j] = cv; cv = tf;
                        int ti = li[j]; li[j] = ci; ci = ti;
                    }
                }
            }
        }
#pragma unroll
        for (int j = 0; j < TOPK; j++) { sv[tid * TOPK + j] = lv[j]; si[tid * TOPK + j] = li[j]; }
        __syncthreads();

        int hp = 0;
        for (int r = 0; r < TOPK; r++) {
            float mv = (hp < TOPK) ? sv[tid * TOPK + hp] : -INFINITY;
            int mi = (hp < TOPK) ? si[tid * TOPK + hp] : 0x7fffffff;
            int myhead = mi;
#pragma unroll
            for (int o = 16; o > 0; o >>= 1) {
                float ov = __shfl_down_sync(0xffffffffu, mv, o);
                int oi = __shfl_down_sync(0xffffffffu, mi, o);
                if (ov > mv || (ov == mv && oi < mi)) { mv = ov; mi = oi; }
            }
            if ((tid & 31) == 0) { swv[tid >> 5] = mv; swi[tid >> 5] = mi; }
            __syncthreads();
            if (tid == 0) {
                float bvv = swv[0]; int bii = swi[0];
#pragma unroll
                for (int w2 = 1; w2 < 8; w2++) {
                    if (swv[w2] > bvv || (swv[w2] == bvv && swi[w2] < bii)) { bvv = swv[w2]; bii = swi[w2]; }
                }
                s_wini = bii;
                d_candv[(b * NCHUNK + c) * TOPK + r] = bvv;
                d_candi[(b * NCHUNK + c) * TOPK + r] = bii;
            }
            __syncthreads();
            if (myhead == s_wini) hp++;
            __syncthreads();
        }
    }
}

// pre2: per-chunk distance sums (reads coordinate sum partials)
__global__ __launch_bounds__(256) void pre2_kernel(
    const float* __restrict__ pts1, const float* __restrict__ pts2, int N) {
    int b = blockIdx.x / NCHUNK;
    int c = blockIdx.x % NCHUNK;
    int L = (N + NCHUNK - 1) / NCHUNK;
    int n0 = c * L;
    int n1 = min(N, n0 + L);
    int tid = threadIdx.x;
    __shared__ double sh[32];

    double sx1 = 0.0, sy1 = 0.0, sx2 = 0.0, sy2 = 0.0;
#pragma unroll
    for (int k = 0; k < NCHUNK; k++) {
        sx1 += d_sum4P[(b * NCHUNK + k) * 4 + 0];
        sy1 += d_sum4P[(b * NCHUNK + k) * 4 + 1];
        sx2 += d_sum4P[(b * NCHUNK + k) * 4 + 2];
        sy2 += d_sum4P[(b * NCHUNK + k) * 4 + 3];
    }
    float fcx1 = (float)(sx1 / N), fcy1 = (float)(sy1 / N);
    float fcx2 = (float)(sx2 / N), fcy2 = (float)(sy2 / N);

    const float* P1 = pts1 + (size_t)b * N * 3;
    const float* P2 = pts2 + (size_t)b * N * 3;
    float ld1 = 0.f, ld2 = 0.f;
    for (int n = n0 + tid; n < n1; n += 256) {
        float dx = P1[n * 3] - fcx1, dy = P1[n * 3 + 1] - fcy1;
        ld1 += fsqrt_fast(dx * dx + dy * dy);
        float ex = P2[n * 3] - fcx2, ey = P2[n * 3 + 1] - fcy2;
        ld2 += fsqrt_fast(ex * ex + ey * ey);
    }
    double d2[2] = { (double)ld1, (double)ld2 };
    blockReduceKD<2>(d2, sh);
    if (tid == 0) {
        d_dist2P[(b * NCHUNK + c) * 2 + 0] = d2[0];
        d_dist2P[(b * NCHUNK + c) * 2 + 1] = d2[1];
    }
}

// pre3: per-chunk Gram partials + params
__global__ __launch_bounds__(256) void pre3_kernel(
    const float* __restrict__ pts1, const float* __restrict__ pts2,
    const float* __restrict__ wt, int N) {
    int b = blockIdx.x / NCHUNK;
    int c = blockIdx.x % NCHUNK;
    int L = (N + NCHUNK - 1) / NCHUNK;
    int n0 = c * L;
    int n1 = min(N, n0 + L);
    int tid = threadIdx.x;
    __shared__ float sG[8][45];

    double sx1 = 0.0, sy1 = 0.0, sx2 = 0.0, sy2 = 0.0, sd1 = 0.0, sd2 = 0.0;
#pragma unroll
    for (int k = 0; k < NCHUNK; k++) {
        sx1 += d_sum4P[(b * NCHUNK + k) * 4 + 0];
        sy1 += d_sum4P[(b * NCHUNK + k) * 4 + 1];
        sx2 += d_sum4P[(b * NCHUNK + k) * 4 + 2];
        sy2 += d_sum4P[(b * NCHUNK + k) * 4 + 3];
        sd1 += d_dist2P[(b * NCHUNK + k) * 2 + 0];
        sd2 += d_dist2P[(b * NCHUNK + k) * 2 + 1];
    }
    double cx1 = sx1 / N, cy1 = sy1 / N, cx2 = sx2 / N, cy2 = sy2 / N;
    double md1 = sd1 / N, md2 = sd2 / N;
    double s1 = 1.4142 / md1, s2 = 1.4142 / md2;
    float fcx1 = (float)cx1, fcy1 = (float)cy1, fcx2 = (float)cx2, fcy2 = (float)cy2;
    float fs1 = (float)s1, fs2 = (float)s2;

    const float* P1 = pts1 + (size_t)b * N * 3;
    const float* P2 = pts2 + (size_t)b * N * 3;
    const float* W = wt + (size_t)b * N;

    float g[45];
#pragma unroll
    for (int i = 0; i < 45; i++) g[i] = 0.f;
    for (int n = n0 + tid; n < n1; n += 256) {
        float z1 = P1[n * 3 + 2], z2 = P2[n * 3 + 2];
        float a1 = fs1 * (P1[n * 3] - fcx1 * z1);
        float a2 = fs1 * (P1[n * 3 + 1] - fcy1 * z1);
        float a3 = z1;
        float b1 = fs2 * (P2[n * 3] - fcx2 * z2);
        float b2 = fs2 * (P2[n * 3 + 1] - fcy2 * z2);
        float p[9] = { b1 * a1, b1 * a2, b1 * a3, b2 * a1, b2 * a2, b2 * a3, a1, a2, a3 };
        float nn = 0.f;
#pragma unroll
        for (int i = 0; i < 9; i++) nn += p[i] * p[i];
        float sc = W[n] * rsqrtf(fmaxf(nn, 1e-37f));
#pragma unroll
        for (int i = 0; i < 9; i++) p[i] *= sc;
        int cc = 0;
#pragma unroll
        for (int i = 0; i < 9; i++)
#pragma unroll
            for (int j = i; j < 9; j++) g[cc++] += p[i] * p[j];
    }
    int wi = tid >> 5, li = tid & 31;
#pragma unroll
    for (int i = 0; i < 45; i++) {
        float x = g[i];
        for (int o = 16; o > 0; o >>= 1) x += __shfl_down_sync(0xffffffffu, x, o);
        if (li == 0) sG[wi][i] = x;
    }
    __syncthreads();
    if (tid < 45) {
        double a = 0.0;
        for (int u2 = 0; u2 < 8; u2++) a += (double)sG[u2][tid];
        d_gramP[(b * NCHUNK + c) * 45 + tid] = (float)a;
    }
    if (c == 0 && tid == 0) {
        d_prmf[b * 6 + 0] = fs1; d_prmf[b * 6 + 1] = fcx1; d_prmf[b * 6 + 2] = fcy1;
        d_prmf[b * 6 + 3] = fs2; d_prmf[b * 6 + 4] = fcx2; d_prmf[b * 6 + 5] = fcy2;
        d_prmd[b * 6 + 0] = s1; d_prmd[b * 6 + 1] = cx1; d_prmd[b * 6 + 2] = cy1;
        d_prmd[b * 6 + 3] = s2; d_prmd[b * 6 + 4] = cx2; d_prmd[b * 6 + 5] = cy2;
    }
}

// =============================== solve helper ===============================

__device__ __forceinline__ void gather_solve20(
    const float* __restrict__ P1b, const float* __restrict__ P2b,
    const float* __restrict__ Wb, const int* __restrict__ idxp,
    float* stash,
    float v[9], float& s1o, float& cx1o, float& cy1o,
    float& s2o, float& cx2o, float& cy2o) {
    float sx1 = 0.f, sy1 = 0.f, sx2 = 0.f, sy2 = 0.f;
#pragma unroll
    for (int k = 0; k < TOPK; k++) {
        int n = idxp[k];
        const float* p1 = P1b + (size_t)n * 3;
        const float* p2 = P2b + (size_t)n * 3;
        sx1 += p1[0]; sy1 += p1[1];
        sx2 += p2[0]; sy2 += p2[1];
    }
    float cx1 = sx1 / TOPK, cy1 = sy1 / TOPK, cx2 = sx2 / TOPK, cy2 = sy2 / TOPK;

    float sd1 = 0.f, sd2 = 0.f;
#pragma unroll
    for (int k = 0; k < TOPK; k++) {
        int n = idxp[k];
        const float* p1 = P1b + (size_t)n * 3;
        const float* p2 = P2b + (size_t)n * 3;
        float dx = p1[0] - cx1, dy = p1[1] - cy1;
        sd1 += fsqrt_fast(dx * dx + dy * dy);
        float ex = p2[0] - cx2, ey = p2[1] - cy2;
        sd2 += fsqrt_fast(ex * ex + ey * ey);
    }
    float s1 = __fdividef(1.4142f * TOPK, sd1);
    float s2 = __fdividef(1.4142f * TOPK, sd2);

    float G45[45];
#pragma unroll
    for (int i = 0; i < 45; i++) G45[i] = 0.f;
#pragma unroll
    for (int k = 0; k < TOPK; k++) {
        int n = idxp[k];
        const float* p1 = P1b + (size_t)n * 3;
        const float* p2 = P2b + (size_t)n * 3;
        float z1 = p1[2], z2 = p2[2];
        float a1 = s1 * (p1[0] - cx1 * z1);
        float a2 = s1 * (p1[1] - cy1 * z1);
        float a3 = z1;
        float b1 = s2 * (p2[0] - cx2 * z2);
        float b2 = s2 * (p2[1] - cy2 * z2);
        float p[9] = { b1 * a1, b1 * a2, b1 * a3, b2 * a1, b2 * a2, b2 * a3, a1, a2, a3 };
        float nn = 0.f;
#pragma unroll
        for (int i = 0; i < 9; i++) nn += p[i] * p[i];
        float sc = Wb[n] * rsqrtf(fmaxf(nn, 1e-37f));
#pragma unroll
        for (int i = 0; i < 9; i++) p[i] *= sc;
        int c = 0;
#pragma unroll
        for (int i = 0; i < 9; i++)
#pragma unroll
            for (int j = i; j < 9; j++) G45[c++] += p[i] * p[j];
    }

    solve9reg(G45, stash, v);
    sign_fix9f(v);
    s1o = s1; cx1o = cx1; cy1o = cy1;
    s2o = s2; cx2o = cx2; cy2o = cy2;
}

// =============================== kernels ===============================

// residual + fused waccu (blocks < B also normalize d_prod)
__global__ void residual_kernel(const float* __restrict__ pts1, const float* __restrict__ pts2,
                                const float* __restrict__ wt, float* __restrict__ res,
                                float* __restrict__ wacc, int B, int N, int S) {
    __shared__ double sh[8];
    int i = blockIdx.x * blockDim.x + threadIdx.x;
    if (i < B * N) {
        int b = i / N;
        const float* pr = d_prmf + b * 6;
        float s1 = pr[0], cx1 = pr[1], cy1 = pr[2];
        float s2 = pr[3], cx2 = pr[4], cy2 = pr[5];
        float vf[9];
#pragma unroll
        for (int k = 0; k < 9; k++) vf[k] = d_vfullf[b * 9 + k];
        const float* p1 = pts1 + (size_t)i * 3;
        const float* p2 = pts2 + (size_t)i * 3;
        float z1 = p1[2], z2 = p2[2];
        float a1 = s1 * (p1[0] - cx1 * z1), a2 = s1 * (p1[1] - cy1 * z1), a3 = z1;
        float b1 = s2 * (p2[0] - cx2 * z2), b2 = s2 * (p2[1] - cy2 * z2);
        float p[9] = { b1 * a1, b1 * a2, b1 * a3, b2 * a1, b2 * a2, b2 * a3, a1, a2, a3 };
        float nn = 0.f;
#pragma unroll
        for (int k = 0; k < 9; k++) nn += p[k] * p[k];
        float sc = wt[i] * rsqrtf(fmaxf(nn, 1e-37f));
        float r = 0.f;
#pragma unroll
        for (int k = 0; k < 9; k++) r += p[k] * vf[k];
        res[i] = r * sc;
    }

    int b2 = blockIdx.x;
    if (b2 < B) {
        int tid = threadIdx.x;
        double loc = 0.0;
        for (int s = tid; s < S; s += blockDim.x) loc += (double)((float)d_prod[b2 * S + s]);
        __syncthreads();
        for (int o = 16; o > 0; o >>= 1) loc += __shfl_down_sync(0xffffffffu, loc, o);
        int wi = tid >> 5, li = tid & 31;
        if (li == 0) sh[wi] = loc;
        __syncthreads();
        if (tid == 0) {
            double r = 0.0;
            int nw = (blockDim.x + 31) >> 5;
            for (int i2 = 0; i2 < nw; i2++) r += sh[i2];
            sh[0] = r;
        }
        __syncthreads();
        double tot = sh[0];
        for (int s = tid; s < S; s += blockDim.x) {
            float pf = (float)d_prod[b2 * S + s];
            wacc[b2 * S + s] = (float)((double)pf / (tot + 1e-10));
        }
    }
}

// unified solve: [0, B*S) sampled, [B*S, B*S+B) topk, [B*S+B, B*S+2B) full
__global__ __launch_bounds__(SMALL_BLK) void solve_kernel(
    const float* __restrict__ pts1, const float* __restrict__ pts2,
    const float* __restrict__ wt, const int* __restrict__ sampled,
    float* __restrict__ outfull, float* __restrict__ outk,
    float* __restrict__ resk, float* __restrict__ outs,
    int B, int N, int S) {
    __shared__ float sStash[45 * SMALL_BLK];
    int tid = threadIdx.x;
    int P = blockIdx.x * SMALL_BLK + tid;
    int total = B * S + 2 * B;
    if (P >= total) return;

    if (P >= B * S + B) {
        // ---- full problem: sum Gram partials ----
        int b = P - B * S - B;
        float G45[45];
#pragma unroll
        for (int i = 0; i < 45; i++) {
            double a = 0.0;
#pragma unroll
            for (int k = 0; k < NCHUNK; k++) a += (double)d_gramP[(b * NCHUNK + k) * 45 + i];
            G45[i] = (float)a;
        }
        float v[9];
        solve9reg(G45, sStash + tid, v);
        sign_fix9f(v);
#pragma unroll
        for (int i = 0; i < 9; i++) d_vfullf[b * 9 + i] = v[i];
        const double* pd = d_prmd + b * 6;
        finalize_F(v, pd[0], pd[1], pd[2], pd[3], pd[4], pd[5], outfull + b * 9);
        return;
    }

    bool is_topk = (P >= B * S);
    int b, s = 0;
    const int* idxp;
    int idxl[TOPK];
    if (is_topk) {
        // ---- merge 8 sorted chunk candidate lists into global top-20 ----
        b = P - B * S;
        int heads[NCHUNK];
#pragma unroll
        for (int k = 0; k < NCHUNK; k++) heads[k] = 0;
#pragma unroll 1
        for (int r = 0; r < TOPK; r++) {
            float bv = -INFINITY;
            int bi = 0x7fffffff;
            int bc = 0;
#pragma unroll
            for (int k = 0; k < NCHUNK; k++) {
                int h = heads[k];
                if (h < TOPK) {
                    float vv = d_candv[(b * NCHUNK + k) * TOPK + h];
                    int ii = d_candi[(b * NCHUNK + k) * TOPK + h];
                    if (vv > bv || (vv == bv && ii < bi)) { bv = vv; bi = ii; bc = k; }
                }
            }
            idxl[r] = bi;
            heads[bc]++;
        }
        idxp = idxl;
    } else {
        b = P / S; s = P - b * S;
        idxp = sampled + ((size_t)b * S + s) * TOPK;
    }

    const float* P1b = pts1 + (size_t)b * N * 3;
    const float* P2b = pts2 + (size_t)b * N * 3;
    const float* Wb = wt + (size_t)b * N;

    float v[9], s1, cx1, cy1, s2, cx2, cy2;
    gather_solve20(P1b, P2b, Wb, idxp, sStash + tid,
                   v, s1, cx1, cy1, s2, cx2, cy2);

    float* o = is_topk ? (outk + b * 9) : (outs + ((size_t)b * S + s) * 9);
    finalize_F(v, (double)s1, (double)cx1, (double)cy1,
               (double)s2, (double)cx2, (double)cy2, o);

    if (is_topk) {
#pragma unroll
        for (int k = 0; k < TOPK; k++) {
            int n = idxp[k];
            const float* p1 = P1b + (size_t)n * 3;
            const float* p2 = P2b + (size_t)n * 3;
            float z1 = p1[2], z2 = p2[2];
            float a1 = s1 * (p1[0] - cx1 * z1);
            float a2 = s1 * (p1[1] - cy1 * z1);
            float a3 = z1;
            float b1 = s2 * (p2[0] - cx2 * z2);
            float b2 = s2 * (p2[1] - cy2 * z2);
            float p[9] = { b1 * a1, b1 * a2, b1 * a3, b2 * a1, b2 * a2, b2 * a3, a1, a2, a3 };
            float nn = 0.f;
#pragma unroll
            for (int i = 0; i < 9; i++) nn += p[i] * p[i];
            float sc = Wb[n] * rsqrtf(fmaxf(nn, 1e-37f));
            float r = 0.f;
#pragma unroll
            for (int i = 0; i < 9; i++) r += p[i] * v[i];
            resk[b * TOPK + k] = r * sc;
        }
    } else {
        double pr = 1.0;
#pragma unroll
        for (int k = 0; k < TOPK; k++) pr *= (double)Wb[idxp[k]] * 1000.0;
        d_prod[b * S + s] = pr;
    }
}

// =============================== launch ===============================

extern "C" void kernel_launch(void* const* d_in, const int* in_sizes, int n_in,
                              void* d_out, int out_size) {
    const float* pts1 = (const float*)d_in[0];
    const float* pts2 = (const float*)d_in[1];
    const float* wt   = (const float*)d_in[2];
    const int*   un   = (const int*)d_in[3];
    const int*   sampled = (const int*)d_in[4];

    int B = in_sizes[3];
    int N = in_sizes[2] / B;
    int S = in_sizes[4] / (B * TOPK);

    float* out = (float*)d_out;
    size_t off_out  = 0;
    size_t off_res  = off_out + (size_t)B * 9;
    size_t off_outk = off_res + (size_t)B * N;
    size_t off_resk = off_outk + (size_t)B * 9;
    size_t off_outs = off_resk + (size_t)B * TOPK;
    size_t off_wacc = off_outs + (size_t)B * S * 9;

    pre1_kernel<<<B * NCHUNK, 256>>>(pts1, pts2, wt, un, N);
    pre2_kernel<<<B * NCHUNK, 256>>>(pts1, pts2, N);
    pre3_kernel<<<B * NCHUNK, 256>>>(pts1, pts2, wt, N);
    int total = B * S + 2 * B;
    solve_kernel<<<(total + SMALL_BLK - 1) / SMALL_BLK, SMALL_BLK>>>(
        pts1, pts2, wt, sampled,
        out + off_out, out + off_outk, out + off_resk, out + off_outs, B, N, S);
    residual_kernel<<<(B * N + 255) / 256, 256>>>(
        pts1, pts2, wt, out + off_res, out + off_wacc, B, N, S);
}

// round 15
// speedup vs baseline: 2.4402x; 2.4402x over previous
#include <cuda_runtime.h>
#include <math.h>

#define TOPK 20
#define MAXB 128
#define MAXS 100
#define SMALL_BLK 64

// ---- device scratch (static; no allocations allowed) ----
__device__ float  d_prmf[MAXB * 6];
__device__ double d_prmd[MAXB * 6];
__device__ float  d_G45full[MAXB * 45];
__device__ float  d_vfullf[MAXB * 9];
__device__ int    d_topkidx[MAXB * TOPK];
__device__ double d_prod[MAXB * MAXS];

__device__ __forceinline__ float fsqrt_fast(float x) {
    return x * rsqrtf(fmaxf(x, 1e-30f));
}

#define IXU(i, j) ((i) * 9 - (i) * ((i) - 1) / 2 + ((j) - (i)))
#define IXE(k, p) (((k) < (p)) ? IXU(k, p) : IXU(p, k))

// =============================== 9x9 smallest-eig solver ===============================
// Register Jacobi (eigenvalues only) + PD-shifted LDL^T (register-resident, static
// indexing) + 2 inverse-iteration solves. stash = strided shared for G45.
__device__ void solve9reg(const float G45in[45], float* stash, float v[9]) {
#pragma unroll
    for (int i = 0; i < 45; i++) stash[i * SMALL_BLK] = G45in[i];

    float U[45];
#pragma unroll
    for (int i = 0; i < 45; i++) U[i] = G45in[i];

#pragma unroll 1
    for (int sweep = 0; sweep < 10; sweep++) {
        float off = 0.f, dd = 0.f;
#pragma unroll
        for (int p = 0; p < 9; p++) {
            dd += fabsf(U[IXU(p, p)]);
#pragma unroll
            for (int q = p + 1; q < 9; q++) off += fabsf(U[IXU(p, q)]);
        }
        if (off <= 1e-7f * dd) break;
#pragma unroll
        for (int p = 0; p < 8; p++) {
#pragma unroll
            for (int q = p + 1; q < 9; q++) {
                float apq = U[IXU(p, q)];
                float app = U[IXU(p, p)], aqq = U[IXU(q, q)];
                float d = aqq - app;
                float sum = d * d + 4.f * apq * apq;
                float ir = rsqrtf(fmaxf(sum, 1e-37f));
                bool ok = (sum >= 1e-30f);
                float c2 = ok ? (0.5f + 0.5f * fabsf(d) * ir) : 1.f;
                float sgn = (d >= 0.f) ? 1.f : -1.f;
                float sc = ok ? (apq * sgn * ir) : 0.f;
                float icc = rsqrtf(c2);
                float cc = c2 * icc;
                float ss = sc * icc;
                float s2 = 1.f - c2;
                float t2 = 2.f * sc * apq;
                U[IXU(p, p)] = c2 * app + s2 * aqq - t2;
                U[IXU(q, q)] = s2 * app + c2 * aqq + t2;
                U[IXU(p, q)] = 0.f;
#pragma unroll
                for (int k = 0; k < 9; k++) {
                    if (k != p && k != q) {
                        float akp = U[IXE(k, p)], akq = U[IXE(k, q)];
                        U[IXE(k, p)] = cc * akp - ss * akq;
                        U[IXE(k, q)] = ss * akp + cc * akq;
                    }
                }
            }
        }
    }
    float lam = U[IXU(0, 0)];
    float dia = fabsf(U[IXU(0, 0)]);
#pragma unroll
    for (int i = 1; i < 9; i++) {
        lam = fminf(lam, U[IXU(i, i)]);
        dia += fabsf(U[IXU(i, i)]);
    }

    // ---- shifted LDL^T in registers (PD: shift sits below lambda_min) ----
    float L[45];
#pragma unroll
    for (int i = 0; i < 45; i++) L[i] = stash[i * SMALL_BLK];
    float shift = lam - 2e-7f * dia - 1e-32f;
#pragma unroll
    for (int i = 0; i < 9; i++) L[IXU(i, i)] -= shift;

    float idg[9];
    float eps_piv = 1e-9f * dia + 1e-35f;
#pragma unroll
    for (int k = 0; k < 9; k++) {
        float d = fmaxf(L[IXU(k, k)], eps_piv);
        float inv = __fdividef(1.f, d);
        idg[k] = inv;
#pragma unroll
        for (int i = k + 1; i < 9; i++) {
            float lik = L[IXU(k, i)] * inv;
#pragma unroll
            for (int j = i; j < 9; j++)
                L[IXU(i, j)] -= lik * L[IXU(k, j)];
            L[IXU(k, i)] = lik;
        }
    }

    float x[9];
#pragma unroll
    for (int i = 0; i < 9; i++) x[i] = 1.f;
#pragma unroll 1
    for (int pass = 0; pass < 2; pass++) {
#pragma unroll
        for (int k = 0; k < 9; k++)
#pragma unroll
            for (int i = k + 1; i < 9; i++)
                x[i] -= L[IXU(k, i)] * x[k];
#pragma unroll
        for (int i = 0; i < 9; i++) x[i] *= idg[i];
#pragma unroll
        for (int k = 8; k >= 0; k--)
#pragma unroll
            for (int j = k + 1; j < 9; j++)
                x[k] -= L[IXU(k, j)] * x[j];
        float am = 0.f;
#pragma unroll
        for (int i = 0; i < 9; i++) am = fmaxf(am, fabsf(x[i]));
        float iam = __fdividef(1.f, am + 1e-37f);
        float n2 = 0.f;
#pragma unroll
        for (int i = 0; i < 9; i++) { float y = x[i] * iam; x[i] = y; n2 += y * y; }
        float inr = rsqrtf(n2);
#pragma unroll
        for (int i = 0; i < 9; i++) x[i] *= inr;
    }
#pragma unroll
    for (int i = 0; i < 9; i++) v[i] = x[i];
}

__device__ __forceinline__ void sign_fix9f(float v[9]) {
    float am = fabsf(v[0]);
    float sv = v[0];
#pragma unroll
    for (int i = 1; i < 9; i++) {
        float a = fabsf(v[i]);
        if (a > am) { am = a; sv = v[i]; }
    }
    if (sv < 0.f) {
#pragma unroll
        for (int i = 0; i < 9; i++) v[i] = -v[i];
    }
}

__device__ void jacobi3f(float* A, float* V) {
#pragma unroll
    for (int i = 0; i < 9; i++) V[i] = (i % 4 == 0) ? 1.f : 0.f;
#define ROT3(p, q)                                                        \
    {                                                                     \
        float apq = A[(p) * 3 + (q)];                                     \
        float app = A[(p) * 3 + (p)], aqq = A[(q) * 3 + (q)];             \
        float d = aqq - app;                                              \
        float sum = d * d + 4.f * apq * apq;                              \
        float ir = rsqrtf(fmaxf(sum, 1e-37f));                            \
        bool ok = (sum >= 1e-30f) && (fabsf(apq) > 1e-30f);               \
        float c2 = ok ? (0.5f + 0.5f * fabsf(d) * ir) : 1.f;              \
        float sgn = (d >= 0.f) ? 1.f : -1.f;                              \
        float sc = ok ? (apq * sgn * ir) : 0.f;                           \
        float icc = rsqrtf(c2);                                           \
        float cc = c2 * icc, ss = sc * icc;                               \
        _Pragma("unroll") for (int k = 0; k < 3; k++) {                   \
            float akp = A[k * 3 + (p)], akq = A[k * 3 + (q)];             \
            A[k * 3 + (p)] = cc * akp - ss * akq;                         \
            A[k * 3 + (q)] = ss * akp + cc * akq;                         \
        }                                                                 \
        _Pragma("unroll") for (int k = 0; k < 3; k++) {                   \
            float apk = A[(p) * 3 + k], aqk = A[(q) * 3 + k];             \
            A[(p) * 3 + k] = cc * apk - ss * aqk;                         \
            A[(q) * 3 + k] = ss * apk + cc * aqk;                         \
        }                                                                 \
        _Pragma("unroll") for (int k = 0; k < 3; k++) {                   \
            float vkp = V[k * 3 + (p)], vkq = V[k * 3 + (q)];             \
            V[k * 3 + (p)] = cc * vkp - ss * vkq;                         \
            V[k * 3 + (q)] = ss * vkp + cc * vkq;                         \
        }                                                                 \
    }
#pragma unroll 1
    for (int sweep = 0; sweep < 8; sweep++) {
        float off = fabsf(A[1]) + fabsf(A[2]) + fabsf(A[5]);
        float dia = fabsf(A[0]) + fabsf(A[4]) + fabsf(A[8]);
        if (off <= 1e-9f * dia) break;
        ROT3(0, 1);
        ROT3(0, 2);
        ROT3(1, 2);
    }
#undef ROT3
}

__device__ void finalize_F(const float vf[9], double s1, double c1x, double c1y,
                           double s2, double c2x, double c2y, float* out9) {
    float F[9];
#pragma unroll
    for (int i = 0; i < 9; i++) F[i] = vf[i];
    float M3[9];
#pragma unroll
    for (int i = 0; i < 3; i++)
#pragma unroll
        for (int j = 0; j < 3; j++) {
            float acc = 0.f;
#pragma unroll
            for (int k = 0; k < 3; k++) acc += F[k * 3 + i] * F[k * 3 + j];
            M3[i * 3 + j] = acc;
        }
    float V3[9];
    jacobi3f(M3, V3);
    float w0 = V3[0], w1 = V3[3], w2 = V3[6];
    float dmin = M3[0];
    if (M3[4] < dmin) { dmin = M3[4]; w0 = V3[1]; w1 = V3[4]; w2 = V3[7]; }
    if (M3[8] < dmin) { w0 = V3[2]; w1 = V3[5]; w2 = V3[8]; }
    float Fw[3];
#pragma unroll
    for (int i = 0; i < 3; i++)
        Fw[i] = F[i * 3 + 0] * w0 + F[i * 3 + 1] * w1 + F[i * 3 + 2] * w2;
    double Fp[9];
#pragma unroll
    for (int i = 0; i < 3; i++) {
        Fp[i * 3 + 0] = (double)(F[i * 3 + 0] - Fw[i] * w0);
        Fp[i * 3 + 1] = (double)(F[i * 3 + 1] - Fw[i] * w1);
        Fp[i * 3 + 2] = (double)(F[i * 3 + 2] - Fw[i] * w2);
    }
    double A[9];
#pragma unroll
    for (int i = 0; i < 3; i++) {
        A[i * 3 + 0] = s1 * Fp[i * 3 + 0];
        A[i * 3 + 1] = s1 * Fp[i * 3 + 1];
        A[i * 3 + 2] = -c1x * s1 * Fp[i * 3 + 0] - c1y * s1 * Fp[i * 3 + 1] + Fp[i * 3 + 2];
    }
#pragma unroll
    for (int j = 0; j < 3; j++) {
        out9[0 * 3 + j] = (float)(s2 * A[0 * 3 + j]);
        out9[1 * 3 + j] = (float)(s2 * A[1 * 3 + j]);
        out9[2 * 3 + j] = (float)(-c2x * s2 * A[0 * 3 + j] - c2y * s2 * A[1 * 3 + j] + A[2 * 3 + j]);
    }
}

// =============================== reductions ===============================

__device__ double blockReduceD(double v, double* sh) {
    __syncthreads();
    for (int o = 16; o > 0; o >>= 1) v += __shfl_down_sync(0xffffffffu, v, o);
    int wi = threadIdx.x >> 5, li = threadIdx.x & 31;
    if (li == 0) sh[wi] = v;
    __syncthreads();
    if (threadIdx.x == 0) {
        double r = 0.0;
        int nw = (blockDim.x + 31) >> 5;
        for (int i = 0; i < nw; i++) r += sh[i];
        sh[0] = r;
    }
    __syncthreads();
    return sh[0];
}

// =============================== kernels ===============================

// full-problem reductions (256 threads/block — measured-fast R8 form)
__global__ __launch_bounds__(256) void full_reduce_kernel(
    const float* __restrict__ pts1, const float* __restrict__ pts2,
    const float* __restrict__ wt, int N) {
    int b = blockIdx.x;
    int tid = threadIdx.x;
    __shared__ double sh[8];
    __shared__ float sG[8][45];

    const float* P1 = pts1 + (size_t)b * N * 3;
    const float* P2 = pts2 + (size_t)b * N * 3;
    const float* W = wt + (size_t)b * N;

    float lx1 = 0.f, ly1 = 0.f, lx2 = 0.f, ly2 = 0.f;
    for (int n = tid; n < N; n += 256) {
        lx1 += P1[n * 3 + 0]; ly1 += P1[n * 3 + 1];
        lx2 += P2[n * 3 + 0]; ly2 += P2[n * 3 + 1];
    }
    double cx1 = blockReduceD((double)lx1, sh) / N;
    double cy1 = blockReduceD((double)ly1, sh) / N;
    double cx2 = blockReduceD((double)lx2, sh) / N;
    double cy2 = blockReduceD((double)ly2, sh) / N;

    float fcx1 = (float)cx1, fcy1 = (float)cy1, fcx2 = (float)cx2, fcy2 = (float)cy2;
    float ld1 = 0.f, ld2 = 0.f;
    for (int n = tid; n < N; n += 256) {
        float dx = P1[n * 3] - fcx1, dy = P1[n * 3 + 1] - fcy1;
        ld1 += fsqrt_fast(dx * dx + dy * dy);
        float ex = P2[n * 3] - fcx2, ey = P2[n * 3 + 1] - fcy2;
        ld2 += fsqrt_fast(ex * ex + ey * ey);
    }
    double md1 = blockReduceD((double)ld1, sh) / N;
    double md2 = blockReduceD((double)ld2, sh) / N;
    double s1 = 1.4142 / md1, s2 = 1.4142 / md2;
    float fs1 = (float)s1, fs2 = (float)s2;

    float g[45];
#pragma unroll
    for (int i = 0; i < 45; i++) g[i] = 0.f;
    for (int n = tid; n < N; n += 256) {
        float z1 = P1[n * 3 + 2], z2 = P2[n * 3 + 2];
        float a1 = fs1 * (P1[n * 3] - fcx1 * z1);
        float a2 = fs1 * (P1[n * 3 + 1] - fcy1 * z1);
        float a3 = z1;
        float b1 = fs2 * (P2[n * 3] - fcx2 * z2);
        float b2 = fs2 * (P2[n * 3 + 1] - fcy2 * z2);
        float p[9] = { b1 * a1, b1 * a2, b1 * a3, b2 * a1, b2 * a2, b2 * a3, a1, a2, a3 };
        float nn = 0.f;
#pragma unroll
        for (int i = 0; i < 9; i++) nn += p[i] * p[i];
        float sc = W[n] * rsqrtf(fmaxf(nn, 1e-37f));
#pragma unroll
        for (int i = 0; i < 9; i++) p[i] *= sc;
        int c = 0;
#pragma unroll
        for (int i = 0; i < 9; i++)
#pragma unroll
            for (int j = i; j < 9; j++) g[c++] += p[i] * p[j];
    }
    int wi = tid >> 5, li = tid & 31;
#pragma unroll
    for (int i = 0; i < 45; i++) {
        float x = g[i];
        for (int o = 16; o > 0; o >>= 1) x += __shfl_down_sync(0xffffffffu, x, o);
        if (li == 0) sG[wi][i] = x;
    }
    __syncthreads();
    if (tid < 45) {
        double a = 0.0;
        for (int u2 = 0; u2 < 8; u2++) a += (double)sG[u2][tid];
        d_G45full[b * 45 + tid] = (float)a;
    }
    if (tid == 0) {
        d_prmf[b * 6 + 0] = (float)s1; d_prmf[b * 6 + 1] = (float)cx1; d_prmf[b * 6 + 2] = (float)cy1;
        d_prmf[b * 6 + 3] = (float)s2; d_prmf[b * 6 + 4] = (float)cx2; d_prmf[b * 6 + 5] = (float)cy2;
        d_prmd[b * 6 + 0] = s1; d_prmd[b * 6 + 1] = cx1; d_prmd[b * 6 + 2] = cy1;
        d_prmd[b * 6 + 3] = s2; d_prmd[b * 6 + 4] = cx2; d_prmd[b * 6 + 5] = cy2;
    }
}

// per-thread register top-20 + 20 merge rounds (measured-fast R8 form)
__global__ __launch_bounds__(256) void topk_kernel(const float* __restrict__ wt,
                                                   const int* __restrict__ un, int N) {
    __shared__ float sv[256 * TOPK];
    __shared__ int si[256 * TOPK];
    __shared__ float swv[8];
    __shared__ int swi[8];
    __shared__ int s_wini;
    int b = blockIdx.x;
    int tid = threadIdx.x;
    int u = un[b];
    const float* W = wt + (size_t)b * N;

    float lv[TOPK];
    int li[TOPK];
#pragma unroll
    for (int j = 0; j < TOPK; j++) { lv[j] = -INFINITY; li[j] = 0x7fffffff; }
    for (int n = tid; n < N; n += 256) {
        float w = (n < u) ? W[n] : -INFINITY;
        if (w > lv[TOPK - 1]) {
            float cv = w; int ci = n;
#pragma unroll
            for (int j = 0; j < TOPK; j++) {
                if (cv > lv[j]) {
                    float tf = lv[j]; lv[j] = cv; cv = tf;
                    int ti = li[j]; li[j] = ci; ci = ti;
                }
            }
        }
    }
#pragma unroll
    for (int j = 0; j < TOPK; j++) { sv[tid * TOPK + j] = lv[j]; si[tid * TOPK + j] = li[j]; }
    __syncthreads();

    int hp = 0;
    for (int r = 0; r < TOPK; r++) {
        float mv = (hp < TOPK) ? sv[tid * TOPK + hp] : -INFINITY;
        int mi = (hp < TOPK) ? si[tid * TOPK + hp] : 0x7fffffff;
        int myhead = mi;
#pragma unroll
        for (int o = 16; o > 0; o >>= 1) {
            float ov = __shfl_down_sync(0xffffffffu, mv, o);
            int oi = __shfl_down_sync(0xffffffffu, mi, o);
            if (ov > mv || (ov == mv && oi < mi)) { mv = ov; mi = oi; }
        }
        if ((tid & 31) == 0) { swv[tid >> 5] = mv; swi[tid >> 5] = mi; }
        __syncthreads();
        if (tid == 0) {
            float bvv = swv[0]; int bii = swi[0];
#pragma unroll
            for (int w2 = 1; w2 < 8; w2++) {
                if (swv[w2] > bvv || (swv[w2] == bvv && swi[w2] < bii)) { bvv = swv[w2]; bii = swi[w2]; }
            }
            s_wini = bii;
            d_topkidx[b * TOPK + r] = bii;
        }
        __syncthreads();
        if (myhead == s_wini) hp++;
        __syncthreads();
    }
}

// =============================== solve helper ===============================

__device__ __forceinline__ void gather_solve20(
    const float* __restrict__ P1b, const float* __restrict__ P2b,
    const float* __restrict__ Wb, const int* __restrict__ idxp,
    float* stash,
    float v[9], float& s1o, float& cx1o, float& cy1o,
    float& s2o, float& cx2o, float& cy2o) {
    float sx1 = 0.f, sy1 = 0.f, sx2 = 0.f, sy2 = 0.f;
#pragma unroll
    for (int k = 0; k < TOPK; k++) {
        int n = idxp[k];
        const float* p1 = P1b + (size_t)n * 3;
        const float* p2 = P2b + (size_t)n * 3;
        sx1 += p1[0]; sy1 += p1[1];
        sx2 += p2[0]; sy2 += p2[1];
    }
    float cx1 = sx1 / TOPK, cy1 = sy1 / TOPK, cx2 = sx2 / TOPK, cy2 = sy2 / TOPK;

    float sd1 = 0.f, sd2 = 0.f;
#pragma unroll
    for (int k = 0; k < TOPK; k++) {
        int n = idxp[k];
        const float* p1 = P1b + (size_t)n * 3;
        const float* p2 = P2b + (size_t)n * 3;
        float dx = p1[0] - cx1, dy = p1[1] - cy1;
        sd1 += fsqrt_fast(dx * dx + dy * dy);
        float ex = p2[0] - cx2, ey = p2[1] - cy2;
        sd2 += fsqrt_fast(ex * ex + ey * ey);
    }
    float s1 = __fdividef(1.4142f * TOPK, sd1);
    float s2 = __fdividef(1.4142f * TOPK, sd2);

    float G45[45];
#pragma unroll
    for (int i = 0; i < 45; i++) G45[i] = 0.f;
#pragma unroll
    for (int k = 0; k < TOPK; k++) {
        int n = idxp[k];
        const float* p1 = P1b + (size_t)n * 3;
        const float* p2 = P2b + (size_t)n * 3;
        float z1 = p1[2], z2 = p2[2];
        float a1 = s1 * (p1[0] - cx1 * z1);
        float a2 = s1 * (p1[1] - cy1 * z1);
        float a3 = z1;
        float b1 = s2 * (p2[0] - cx2 * z2);
        float b2 = s2 * (p2[1] - cy2 * z2);
        float p[9] = { b1 * a1, b1 * a2, b1 * a3, b2 * a1, b2 * a2, b2 * a3, a1, a2, a3 };
        float nn = 0.f;
#pragma unroll
        for (int i = 0; i < 9; i++) nn += p[i] * p[i];
        float sc = Wb[n] * rsqrtf(fmaxf(nn, 1e-37f));
#pragma unroll
        for (int i = 0; i < 9; i++) p[i] *= sc;
        int c = 0;
#pragma unroll
        for (int i = 0; i < 9; i++)
#pragma unroll
            for (int j = i; j < 9; j++) G45[c++] += p[i] * p[j];
    }

    solve9reg(G45, stash, v);
    sign_fix9f(v);
    s1o = s1; cx1o = cx1; cy1o = cy1;
    s2o = s2; cx2o = cx2; cy2o = cy2;
}

// residual + fused waccu (blocks < B also normalize d_prod)
__global__ void residual_kernel(const float* __restrict__ pts1, const float* __restrict__ pts2,
                                const float* __restrict__ wt, float* __restrict__ res,
                                float* __restrict__ wacc, int B, int N, int S) {
    __shared__ double sh[8];
    int i = blockIdx.x * blockDim.x + threadIdx.x;
    if (i < B * N) {
        int b = i / N;
        const float* pr = d_prmf + b * 6;
        float s1 = pr[0], cx1 = pr[1], cy1 = pr[2];
        float s2 = pr[3], cx2 = pr[4], cy2 = pr[5];
        float vf[9];
#pragma unroll
        for (int k = 0; k < 9; k++) vf[k] = d_vfullf[b * 9 + k];
        const float* p1 = pts1 + (size_t)i * 3;
        const float* p2 = pts2 + (size_t)i * 3;
        float z1 = p1[2], z2 = p2[2];
        float a1 = s1 * (p1[0] - cx1 * z1), a2 = s1 * (p1[1] - cy1 * z1), a3 = z1;
        float b1 = s2 * (p2[0] - cx2 * z2), b2 = s2 * (p2[1] - cy2 * z2);
        float p[9] = { b1 * a1, b1 * a2, b1 * a3, b2 * a1, b2 * a2, b2 * a3, a1, a2, a3 };
        float nn = 0.f;
#pragma unroll
        for (int k = 0; k < 9; k++) nn += p[k] * p[k];
        float sc = wt[i] * rsqrtf(fmaxf(nn, 1e-37f));
        float r = 0.f;
#pragma unroll
        for (int k = 0; k < 9; k++) r += p[k] * vf[k];
        res[i] = r * sc;
    }

    int b2 = blockIdx.x;
    if (b2 < B) {
        int tid = threadIdx.x;
        double loc = 0.0;
        for (int s = tid; s < S; s += blockDim.x) loc += (double)((float)d_prod[b2 * S + s]);
        __syncthreads();
        for (int o = 16; o > 0; o >>= 1) loc += __shfl_down_sync(0xffffffffu, loc, o);
        int wi = tid >> 5, li = tid & 31;
        if (li == 0) sh[wi] = loc;
        __syncthreads();
        if (tid == 0) {
            double r = 0.0;
            int nw = (blockDim.x + 31) >> 5;
            for (int i2 = 0; i2 < nw; i2++) r += sh[i2];
            sh[0] = r;
        }
        __syncthreads();
        double tot = sh[0];
        for (int s = tid; s < S; s += blockDim.x) {
            float pf = (float)d_prod[b2 * S + s];
            wacc[b2 * S + s] = (float)((double)pf / (tot + 1e-10));
        }
    }
}

// unified solve: [0, B*S) sampled, [B*S, B*S+B) topk, [B*S+B, B*S+2B) full
__global__ __launch_bounds__(SMALL_BLK) void solve_kernel(
    const float* __restrict__ pts1, const float* __restrict__ pts2,
    const float* __restrict__ wt, const int* __restrict__ sampled,
    float* __restrict__ outfull, float* __restrict__ outk,
    float* __restrict__ resk, float* __restrict__ outs,
    int B, int N, int S) {
    __shared__ float sStash[45 * SMALL_BLK];
    int tid = threadIdx.x;
    int P = blockIdx.x * SMALL_BLK + tid;
    int total = B * S + 2 * B;
    if (P >= total) return;

    if (P >= B * S + B) {
        int b = P - B * S - B;
        float G45[45];
#pragma unroll
        for (int i = 0; i < 45; i++) G45[i] = d_G45full[b * 45 + i];
        float v[9];
        solve9reg(G45, sStash + tid, v);
        sign_fix9f(v);
#pragma unroll
        for (int i = 0; i < 9; i++) d_vfullf[b * 9 + i] = v[i];
        const double* pd = d_prmd + b * 6;
        finalize_F(v, pd[0], pd[1], pd[2], pd[3], pd[4], pd[5], outfull + b * 9);
        return;
    }

    bool is_topk = (P >= B * S);
    int b, s = 0;
    const int* idxp;
    if (is_topk) { b = P - B * S; idxp = d_topkidx + b * TOPK; }
    else { b = P / S; s = P - b * S; idxp = sampled + ((size_t)b * S + s) * TOPK; }

    const float* P1b = pts1 + (size_t)b * N * 3;
    const float* P2b = pts2 + (size_t)b * N * 3;
    const float* Wb = wt + (size_t)b * N;

    float v[9], s1, cx1, cy1, s2, cx2, cy2;
    gather_solve20(P1b, P2b, Wb, idxp, sStash + tid,
                   v, s1, cx1, cy1, s2, cx2, cy2);

    float* o = is_topk ? (outk + b * 9) : (outs + ((size_t)b * S + s) * 9);
    finalize_F(v, (double)s1, (double)cx1, (double)cy1,
               (double)s2, (double)cx2, (double)cy2, o);

    if (is_topk) {
#pragma unroll
        for (int k = 0; k < TOPK; k++) {
            int n = idxp[k];
            const float* p1 = P1b + (size_t)n * 3;
            const float* p2 = P2b + (size_t)n * 3;
            float z1 = p1[2], z2 = p2[2];
            float a1 = s1 * (p1[0] - cx1 * z1);
            float a2 = s1 * (p1[1] - cy1 * z1);
            float a3 = z1;
            float b1 = s2 * (p2[0] - cx2 * z2);
            float b2 = s2 * (p2[1] - cy2 * z2);
            float p[9] = { b1 * a1, b1 * a2, b1 * a3, b2 * a1, b2 * a2, b2 * a3, a1, a2, a3 };
            float nn = 0.f;
#pragma unroll
            for (int i = 0; i < 9; i++) nn += p[i] * p[i];
            float sc = Wb[n] * rsqrtf(fmaxf(nn, 1e-37f));
            float r = 0.f;
#pragma unroll
            for (int i = 0; i < 9; i++) r += p[i] * v[i];
            resk[b * TOPK + k] = r * sc;
        }
    } else {
        double pr = 1.0;
#pragma unroll
        for (int k = 0; k < TOPK; k++) pr *= (double)Wb[idxp[k]] * 1000.0;
        d_prod[b * S + s] = pr;
    }
}

// =============================== launch ===============================

extern "C" void kernel_launch(void* const* d_in, const int* in_sizes, int n_in,
                              void* d_out, int out_size) {
    const float* pts1 = (const float*)d_in[0];
    const float* pts2 = (const float*)d_in[1];
    const float* wt   = (const float*)d_in[2];
    const int*   un   = (const int*)d_in[3];
    const int*   sampled = (const int*)d_in[4];

    int B = in_sizes[3];
    int N = in_sizes[2] / B;
    int S = in_sizes[4] / (B * TOPK);

    float* out = (float*)d_out;
    size_t off_out  = 0;
    size_t off_res  = off_out + (size_t)B * 9;
    size_t off_outk = off_res + (size_t)B * N;
    size_t off_resk = off_outk + (size_t)B * 9;
    size_t off_outs = off_resk + (size_t)B * TOPK;
    size_t off_wacc = off_outs + (size_t)B * S * 9;

    full_reduce_kernel<<<B, 256>>>(pts1, pts2, wt, N);
    topk_kernel<<<B, 256>>>(wt, un, N);
    int total = B * S + 2 * B;
    solve_kernel<<<(total + SMALL_BLK - 1) / SMALL_BLK, SMALL_BLK>>>(
        pts1, pts2, wt, sampled,
        out + off_out, out + off_outk, out + off_resk, out + off_outs, B, N, S);
    residual_kernel<<<(B * N + 255) / 256, 256>>>(
        pts1, pts2, wt, out + off_res, out + off_wacc, B, N, S);
}